// round 2
// baseline (speedup 1.0000x reference)
#include <cuda_runtime.h>
#include <math.h>

#define TT 512
#define BB 64
#define DD 1024
#define HH 1024
#define GG 4096   // 4*H

// Scratch (allocation-free rules: __device__ globals)
static __device__ float g_gx[(size_t)TT * BB * GG];   // 512 MB precomputed input gates (+ both biases)
static __device__ float g_c[2][BB * HH];              // ping-pong cell state

// ---------------------------------------------------------------------------
// Phase 1: gates_x[t*B+b, n] = sum_k x[t,b,k]*w_ih[n,k] + b_ih[n] + b_hh[n]
// Classic 128x128x16 fp32 SGEMM, NT layout (both operands K-contiguous).
// ---------------------------------------------------------------------------
__global__ __launch_bounds__(256) void gemm_gx_kernel(
    const float* __restrict__ X,     // [32768, 1024]
    const float* __restrict__ W,     // [4096, 1024]
    const float* __restrict__ bih,
    const float* __restrict__ bhh)
{
    __shared__ float As[16][128];
    __shared__ float Bs[16][128];
    const int bm = blockIdx.y * 128;
    const int bn = blockIdx.x * 128;
    const int tid = threadIdx.x;
    const int trow = (tid >> 4) << 3;   // 0..120
    const int tcol = (tid & 15) << 3;   // 0..120

    float acc[8][8];
#pragma unroll
    for (int i = 0; i < 8; i++)
#pragma unroll
        for (int j = 0; j < 8; j++) acc[i][j] = 0.f;

    for (int k0 = 0; k0 < DD; k0 += 16) {
#pragma unroll
        for (int i = 0; i < 2; i++) {
            int idx = tid + (i << 8);      // 0..511
            int row = idx >> 2;            // 0..127
            int kv  = (idx & 3) << 2;      // 0,4,8,12
            float4 a = *(const float4*)(X + (size_t)(bm + row) * DD + k0 + kv);
            As[kv + 0][row] = a.x; As[kv + 1][row] = a.y;
            As[kv + 2][row] = a.z; As[kv + 3][row] = a.w;
            float4 b = *(const float4*)(W + (size_t)(bn + row) * DD + k0 + kv);
            Bs[kv + 0][row] = b.x; Bs[kv + 1][row] = b.y;
            Bs[kv + 2][row] = b.z; Bs[kv + 3][row] = b.w;
        }
        __syncthreads();
#pragma unroll
        for (int k = 0; k < 16; k++) {
            float a[8], b[8];
#pragma unroll
            for (int i = 0; i < 8; i++) a[i] = As[k][trow + i];
#pragma unroll
            for (int j = 0; j < 8; j++) b[j] = Bs[k][tcol + j];
#pragma unroll
            for (int i = 0; i < 8; i++)
#pragma unroll
                for (int j = 0; j < 8; j++)
                    acc[i][j] = fmaf(a[i], b[j], acc[i][j]);
        }
        __syncthreads();
    }

#pragma unroll
    for (int i = 0; i < 8; i++) {
        size_t m = (size_t)(bm + trow + i);
#pragma unroll
        for (int j = 0; j < 8; j++) {
            int n = bn + tcol + j;
            g_gx[m * GG + n] = acc[i][j] + bih[n] + bhh[n];
        }
    }
}

// ---------------------------------------------------------------------------
// Phase 2: one LSTM step.
// Grid = 128 CTAs, each owns j in [8*blockIdx.x, 8*blockIdx.x+8) and computes
// the 4 gathered gate stripes (i/f/g/o) for all 64 batch rows:
//   gates[b, c] = gx[...] + sum_k h[b,k] * w_hh[wrow(c), k],  c in [0,32)
//   wrow(c) = (c>>3)*H + j0 + (c&7)
// Smem tiles are transposed ([k][·]) with an XOR swizzle (col ^= k&~3) so the
// transpose STS are bank-conflict-free while compute reads stay vectorized
// 16B-aligned broadcasts.
// ---------------------------------------------------------------------------
__global__ __launch_bounds__(256) void lstm_step_kernel(
    int t,
    const float* __restrict__ W,    // w_hh [4096, 1024]
    const float* __restrict__ h0,
    const float* __restrict__ c0,
    float* __restrict__ out)
{
    __shared__ float Hs[32][64];   // [k][b], swizzled
    __shared__ float Ws[32][32];   // [k][c], swizzled

    const float* gx   = g_gx + (size_t)t * BB * GG;
    const float* h_in = (t == 0) ? h0 : out + (size_t)(t - 1) * BB * HH;
    const float* c_in = (t == 0) ? c0 : g_c[(t - 1) & 1];
    float* c_out = g_c[t & 1];
    float* h_out = out + (size_t)t * BB * HH;

    const int j0  = blockIdx.x * 8;
    const int tid = threadIdx.x;
    const int tx  = tid & 15;   // col pair: 2tx, 2tx+1
    const int ty  = tid >> 4;   // rows 4ty .. 4ty+3

    float acc[4][2];
#pragma unroll
    for (int r = 0; r < 4; r++) { acc[r][0] = 0.f; acc[r][1] = 0.f; }

    // preload per-thread W-load indices
    const int wc  = tid >> 3;                 // logical col 0..31
    const int wkv = (tid & 7) << 2;           // 0..28
    const int wrow = (wc >> 3) * HH + j0 + (wc & 7);

    for (int k0 = 0; k0 < HH; k0 += 32) {
        // Load h tile: 64x32 floats, coalesced, swizzled transpose store
#pragma unroll
        for (int i = 0; i < 2; i++) {
            int idx = tid + (i << 8);          // 0..511
            int b   = idx >> 3;                // 0..63
            int kv  = (idx & 7) << 2;          // 0..28
            float4 v = *(const float4*)(h_in + (size_t)b * HH + k0 + kv);
            int col = b ^ kv;                  // swizzle (kv multiple of 4)
            Hs[kv + 0][col] = v.x; Hs[kv + 1][col] = v.y;
            Hs[kv + 2][col] = v.z; Hs[kv + 3][col] = v.w;
        }
        // Load w tile: 32 gathered rows x 32 k
        {
            float4 v = *(const float4*)(W + (size_t)wrow * HH + k0 + wkv);
            int col = wc ^ wkv;
            Ws[wkv + 0][col] = v.x; Ws[wkv + 1][col] = v.y;
            Ws[wkv + 2][col] = v.z; Ws[wkv + 3][col] = v.w;
        }
        __syncthreads();
#pragma unroll
        for (int k = 0; k < 32; k++) {
            int kq = k & 28;
            float2 w2 = *(const float2*)&Ws[k][(2 * tx) ^ kq];
            float4 h4 = *(const float4*)&Hs[k][(4 * ty) ^ kq];
            acc[0][0] = fmaf(h4.x, w2.x, acc[0][0]);
            acc[0][1] = fmaf(h4.x, w2.y, acc[0][1]);
            acc[1][0] = fmaf(h4.y, w2.x, acc[1][0]);
            acc[1][1] = fmaf(h4.y, w2.y, acc[1][1]);
            acc[2][0] = fmaf(h4.z, w2.x, acc[2][0]);
            acc[2][1] = fmaf(h4.z, w2.y, acc[2][1]);
            acc[3][0] = fmaf(h4.w, w2.x, acc[3][0]);
            acc[3][1] = fmaf(h4.w, w2.y, acc[3][1]);
        }
        __syncthreads();
    }

    // Stage gates in smem (reuse Hs: 2048 floats) and add gx
    float (*sg)[32] = reinterpret_cast<float(*)[32]>(&Hs[0][0]);
#pragma unroll
    for (int r = 0; r < 4; r++) {
        int b = 4 * ty + r;
#pragma unroll
        for (int jj = 0; jj < 2; jj++) {
            int c = 2 * tx + jj;
            int gate = c >> 3, jl = c & 7;
            sg[b][c] = acc[r][jj] + gx[(size_t)b * GG + gate * HH + j0 + jl];
        }
    }
    __syncthreads();

    // Pointwise LSTM cell: 512 (b, j) elements per block, 2 per thread
#pragma unroll
    for (int i = 0; i < 2; i++) {
        int idx = tid + (i << 8);      // 0..511
        int b = idx >> 3, jl = idx & 7;
        float gi = sg[b][jl];
        float gf = sg[b][8 + jl];
        float gg = sg[b][16 + jl];
        float go = sg[b][24 + jl];
        float ig = 1.0f / (1.0f + __expf(-gi));
        float fg = 1.0f / (1.0f + __expf(-gf));
        float gv = tanhf(gg);
        float og = 1.0f / (1.0f + __expf(-go));
        float cp = c_in[(size_t)b * HH + j0 + jl];
        float cn = fg * cp + ig * gv;
        float hn = og * tanhf(cn);
        c_out[(size_t)b * HH + j0 + jl] = cn;
        h_out[(size_t)b * HH + j0 + jl] = hn;
    }
}

// ---------------------------------------------------------------------------
// Final states: h_n = hs[T-1], c_n = c ping-pong buffer of step T-1
// ---------------------------------------------------------------------------
__global__ void finalize_kernel(float* __restrict__ out)
{
    int i = blockIdx.x * blockDim.x + threadIdx.x;
    if (i < BB * HH) {
        out[(size_t)TT * BB * HH + i] = out[(size_t)(TT - 1) * BB * HH + i];
        out[(size_t)TT * BB * HH + BB * HH + i] = g_c[(TT - 1) & 1][i];
    }
}

extern "C" void kernel_launch(void* const* d_in, const int* in_sizes, int n_in,
                              void* d_out, int out_size)
{
    const float* x    = (const float*)d_in[0];
    const float* h0   = (const float*)d_in[1];
    const float* c0   = (const float*)d_in[2];
    const float* w_ih = (const float*)d_in[3];
    const float* b_ih = (const float*)d_in[4];
    const float* w_hh = (const float*)d_in[5];
    const float* b_hh = (const float*)d_in[6];
    float* out = (float*)d_out;

    (void)in_sizes; (void)n_in; (void)out_size;

    // Phase 1: big input-projection GEMM (biases folded)
    dim3 g1(GG / 128, (TT * BB) / 128);
    gemm_gx_kernel<<<g1, 256>>>(x, w_ih, b_ih, b_hh);

    // Phase 2: 512 sequential recurrence steps
    for (int t = 0; t < TT; t++)
        lstm_step_kernel<<<HH / 8, 256>>>(t, w_hh, h0, c0, out);

    // Final states
    finalize_kernel<<<(BB * HH + 255) / 256, 256>>>(out);
}

// round 3
// speedup vs baseline: 1.2276x; 1.2276x over previous
#include <cuda_runtime.h>
#include <math.h>

#define TT 512
#define BB 64
#define DD 1024
#define HH 1024
#define GG 4096   // 4*H
#define NCTA 128

// Scratch (allocation-free rules: __device__ globals)
static __device__ float g_gx[(size_t)TT * BB * GG];   // precomputed input gates (+ both biases)
static __device__ unsigned g_arrive = 0;
static __device__ unsigned g_release = 0;

// ---------------------------------------------------------------------------
// Phase 1: gates_x[t*B+b, n] = sum_k x[t,b,k]*w_ih[n,k] + b_ih[n] + b_hh[n]
// 128x128x16 fp32 SGEMM, NT layout.
// ---------------------------------------------------------------------------
__global__ __launch_bounds__(256) void gemm_gx_kernel(
    const float* __restrict__ X,     // [32768, 1024]
    const float* __restrict__ W,     // [4096, 1024]
    const float* __restrict__ bih,
    const float* __restrict__ bhh)
{
    __shared__ float As[16][128];
    __shared__ float Bs[16][128];
    const int bm = blockIdx.y * 128;
    const int bn = blockIdx.x * 128;
    const int tid = threadIdx.x;
    const int trow = (tid >> 4) << 3;
    const int tcol = (tid & 15) << 3;

    float acc[8][8];
#pragma unroll
    for (int i = 0; i < 8; i++)
#pragma unroll
        for (int j = 0; j < 8; j++) acc[i][j] = 0.f;

    for (int k0 = 0; k0 < DD; k0 += 16) {
#pragma unroll
        for (int i = 0; i < 2; i++) {
            int idx = tid + (i << 8);
            int row = idx >> 2;
            int kv  = (idx & 3) << 2;
            float4 a = *(const float4*)(X + (size_t)(bm + row) * DD + k0 + kv);
            As[kv + 0][row] = a.x; As[kv + 1][row] = a.y;
            As[kv + 2][row] = a.z; As[kv + 3][row] = a.w;
            float4 b = *(const float4*)(W + (size_t)(bn + row) * DD + k0 + kv);
            Bs[kv + 0][row] = b.x; Bs[kv + 1][row] = b.y;
            Bs[kv + 2][row] = b.z; Bs[kv + 3][row] = b.w;
        }
        __syncthreads();
#pragma unroll
        for (int k = 0; k < 16; k++) {
            float a[8], b[8];
#pragma unroll
            for (int i = 0; i < 8; i++) a[i] = As[k][trow + i];
#pragma unroll
            for (int j = 0; j < 8; j++) b[j] = Bs[k][tcol + j];
#pragma unroll
            for (int i = 0; i < 8; i++)
#pragma unroll
                for (int j = 0; j < 8; j++)
                    acc[i][j] = fmaf(a[i], b[j], acc[i][j]);
        }
        __syncthreads();
    }

#pragma unroll
    for (int i = 0; i < 8; i++) {
        size_t m = (size_t)(bm + trow + i);
#pragma unroll
        for (int j = 0; j < 8; j++) {
            int n = bn + tcol + j;
            g_gx[m * GG + n] = acc[i][j] + bih[n] + bhh[n];
        }
    }
}

// ---------------------------------------------------------------------------
// Phase 2: persistent recurrence kernel. 128 CTAs (1/SM), 256 threads.
// CTA owns h-columns j0..j0+7 across all 4 gates (32 gathered w_hh rows),
// which live in SMEM for the whole kernel (loaded once). Cell state c lives
// in registers. Grid-wide barrier between steps.
// SMEM: Ws[1024][32] swizzled (128 KB) + Hs[2][64][64] swizzled (32 KB).
// ---------------------------------------------------------------------------
__global__ __launch_bounds__(256, 1) void lstm_persist_kernel(
    const float* __restrict__ W,    // w_hh [4096, 1024]
    const float* __restrict__ h0,
    const float* __restrict__ c0,
    float* __restrict__ out)
{
    extern __shared__ float smem[];
    float* Ws = smem;                 // [1024][32], col swizzled by (k&28)
    float* Hsb = smem + 1024 * 32;    // [2][64][64], col swizzled by (k&28)

    const int tid = threadIdx.x;
    const int tx  = tid & 15;         // out col pair 2tx,2tx+1
    const int ty  = tid >> 4;         // out rows 4ty..4ty+3
    const int j0  = blockIdx.x * 8;

    // Monotonic release base (replay-safe: read before any barrier activity)
    const unsigned rel_base = *(volatile unsigned*)&g_release;

    // ---- Load W slice into SMEM (once) ----
    // 32 gathered rows x 1024 k = 8192 float4; 32 per thread.
#pragma unroll 4
    for (int r = 0; r < 32; r++) {
        int idx = r * 256 + tid;
        int k4  = idx & 255;          // float4 index along k
        int c   = idx >> 8;           // logical col 0..31
        int k   = k4 << 2;
        int row = (c >> 3) * HH + j0 + (c & 7);
        float4 v = *(const float4*)(W + (size_t)row * HH + k);
        int col = c ^ (k & 28);
        Ws[(k + 0) * 32 + col] = v.x;
        Ws[(k + 1) * 32 + col] = v.y;
        Ws[(k + 2) * 32 + col] = v.z;
        Ws[(k + 3) * 32 + col] = v.w;
    }

    // ---- Cell state in registers: 2 (b, jl) elements per thread ----
    // element i: idx = tid + i*256 -> b = idx>>3, jl = idx&7
    float c_reg[2];
#pragma unroll
    for (int i = 0; i < 2; i++) {
        int idx = tid + (i << 8);
        int b = idx >> 3, jl = idx & 7;
        c_reg[i] = c0[(size_t)b * HH + j0 + jl];
    }
    __syncthreads();

    // h-load per-thread geometry: 4 float4 per tile
    const int hkv = tx << 2;          // local k offset 0..60
    // rows: ty + 16r

    for (int t = 0; t < TT; t++) {
        const float* __restrict__ h_in =
            (t == 0) ? h0 : out + (size_t)(t - 1) * BB * HH;
        const float* __restrict__ gx = g_gx + (size_t)t * BB * GG;

        // Prefetch gx for the pointwise stage (8 scattered loads, DRAM,
        // hidden under ~16us of FMA)
        float gpre[2][4];
#pragma unroll
        for (int i = 0; i < 2; i++) {
            int idx = tid + (i << 8);
            int b = idx >> 3, jl = idx & 7;
            const float* gr = gx + (size_t)b * GG + j0 + jl;
#pragma unroll
            for (int g = 0; g < 4; g++) gpre[i][g] = gr[g * HH];
        }

        float acc[4][2];
#pragma unroll
        for (int r = 0; r < 4; r++) { acc[r][0] = 0.f; acc[r][1] = 0.f; }

        // Preload tile 0
        {
            const float* hsrc = h_in + hkv;
#pragma unroll
            for (int r = 0; r < 4; r++) {
                float4 v = *(const float4*)(hsrc + (size_t)(ty + 16 * r) * HH);
                int col = (ty + 16 * r) ^ (hkv & 28);
                float* dst = Hsb + (hkv * 64) + col;
                dst[0]   = v.x; dst[64]  = v.y;
                dst[128] = v.z; dst[192] = v.w;
            }
        }
        __syncthreads();

        for (int it = 0; it < 16; ++it) {
            float4 pre[4];
            if (it < 15) {
                const float* hsrc = h_in + (it + 1) * 64 + hkv;
#pragma unroll
                for (int r = 0; r < 4; r++)
                    pre[r] = *(const float4*)(hsrc + (size_t)(ty + 16 * r) * HH);
            }
            const float* cur = Hsb + (it & 1) * 4096;
            const float* WsK = Ws + (it * 64) * 32;
#pragma unroll
            for (int kk = 0; kk < 64; kk++) {
                int kq = kk & 28;
                float2 w2 = *(const float2*)(WsK + kk * 32 + ((2 * tx) ^ kq));
                float4 h4 = *(const float4*)(cur + kk * 64 + ((4 * ty) ^ kq));
                acc[0][0] = fmaf(h4.x, w2.x, acc[0][0]);
                acc[0][1] = fmaf(h4.x, w2.y, acc[0][1]);
                acc[1][0] = fmaf(h4.y, w2.x, acc[1][0]);
                acc[1][1] = fmaf(h4.y, w2.y, acc[1][1]);
                acc[2][0] = fmaf(h4.z, w2.x, acc[2][0]);
                acc[2][1] = fmaf(h4.z, w2.y, acc[2][1]);
                acc[3][0] = fmaf(h4.w, w2.x, acc[3][0]);
                acc[3][1] = fmaf(h4.w, w2.y, acc[3][1]);
            }
            __syncthreads();
            if (it < 15) {
                float* nxt = Hsb + ((it + 1) & 1) * 4096;
#pragma unroll
                for (int r = 0; r < 4; r++) {
                    int col = (ty + 16 * r) ^ (hkv & 28);
                    float* dst = nxt + hkv * 64 + col;
                    dst[0]   = pre[r].x; dst[64]  = pre[r].y;
                    dst[128] = pre[r].z; dst[192] = pre[r].w;
                }
                __syncthreads();
            }
        }

        // Stage matmul results to smem (pad stride 33 to ease bank conflicts)
        float* sg = Hsb;  // reuse buffer 0: 64*33 floats = 8448 < 4096*2
#pragma unroll
        for (int r = 0; r < 4; r++) {
#pragma unroll
            for (int jj = 0; jj < 2; jj++)
                sg[(4 * ty + r) * 33 + (2 * tx + jj)] = acc[r][jj];
        }
        __syncthreads();

        // Pointwise LSTM cell
        float* h_out = out + (size_t)t * BB * HH;
#pragma unroll
        for (int i = 0; i < 2; i++) {
            int idx = tid + (i << 8);
            int b = idx >> 3, jl = idx & 7;
            float gi = sg[b * 33 + jl]      + gpre[i][0];
            float gf = sg[b * 33 + 8 + jl]  + gpre[i][1];
            float gg = sg[b * 33 + 16 + jl] + gpre[i][2];
            float go = sg[b * 33 + 24 + jl] + gpre[i][3];
            float ig = 1.0f / (1.0f + __expf(-gi));
            float fg = 1.0f / (1.0f + __expf(-gf));
            float gv = tanhf(gg);
            float og = 1.0f / (1.0f + __expf(-go));
            float cn = fg * c_reg[i] + ig * gv;
            float hn = og * tanhf(cn);
            c_reg[i] = cn;
            h_out[(size_t)b * HH + j0 + jl] = hn;
            if (t == TT - 1) {
                // h_n
                out[(size_t)TT * BB * HH + (size_t)b * HH + j0 + jl] = hn;
                // c_n
                out[(size_t)TT * BB * HH + BB * HH + (size_t)b * HH + j0 + jl] = cn;
            }
        }

        // Grid-wide barrier (skip after the last step)
        if (t < TT - 1) {
            __threadfence();
            __syncthreads();
            if (tid == 0) {
                unsigned target = rel_base + (unsigned)(t + 1);
                unsigned old = atomicAdd(&g_arrive, 1);
                if (old == NCTA - 1) {
                    g_arrive = 0;           // safe: no one arrives until release
                    __threadfence();
                    *(volatile unsigned*)&g_release = target;
                } else {
                    while ((int)(*(volatile unsigned*)&g_release - target) < 0) {}
                    __threadfence();
                }
            }
            __syncthreads();
        }
    }
}

extern "C" void kernel_launch(void* const* d_in, const int* in_sizes, int n_in,
                              void* d_out, int out_size)
{
    const float* x    = (const float*)d_in[0];
    const float* h0   = (const float*)d_in[1];
    const float* c0   = (const float*)d_in[2];
    const float* w_ih = (const float*)d_in[3];
    const float* b_ih = (const float*)d_in[4];
    const float* w_hh = (const float*)d_in[5];
    const float* b_hh = (const float*)d_in[6];
    float* out = (float*)d_out;

    (void)in_sizes; (void)n_in; (void)out_size;

    // Phase 1: big input-projection GEMM (biases folded)
    dim3 g1(GG / 128, (TT * BB) / 128);
    gemm_gx_kernel<<<g1, 256>>>(x, w_ih, b_ih, b_hh);

    // Phase 2: persistent recurrence (whole scan in one kernel)
    const int smem_bytes = (1024 * 32 + 2 * 64 * 64) * (int)sizeof(float); // 160 KB
    cudaFuncSetAttribute(lstm_persist_kernel,
                         cudaFuncAttributeMaxDynamicSharedMemorySize, smem_bytes);
    lstm_persist_kernel<<<NCTA, 256, smem_bytes>>>(w_hh, h0, c0, out);
}

// round 4
// speedup vs baseline: 1.2392x; 1.0094x over previous
#include <cuda_runtime.h>
#include <math.h>
#include <stdint.h>

#define TT 512
#define BB 64
#define DD 1024
#define HH 1024
#define GG 4096   // 4*H
#define NCTA 128

// Scratch (allocation-free rules: __device__ globals)
static __device__ float g_gx[(size_t)TT * BB * GG];   // precomputed input gates (+ both biases)
static __device__ unsigned g_arrive = 0;
static __device__ unsigned g_release = 0;

// Packed fp32x2 helpers (sm_103a FFMA2 — 2 exact fp32 FMAs per issue)
#define FFMA2(acc, a, b) \
    asm("fma.rn.f32x2 %0, %1, %2, %0;" : "+l"(acc) : "l"(a), "l"(b))
#define DUP2(dst, s) \
    asm("mov.b64 %0, {%1, %1};" : "=l"(dst) : "f"(s))
#define UNPK2(lo, hi, src) \
    asm("mov.b64 {%0, %1}, %2;" : "=f"(lo), "=f"(hi) : "l"(src))

// ---------------------------------------------------------------------------
// Phase 1: gates_x[t*B+b, n] = sum_k x[t,b,k]*w_ih[n,k] + b_ih[n] + b_hh[n]
// 128x128x16 fp32 SGEMM, NT layout, FFMA2 inner product.
// ---------------------------------------------------------------------------
__global__ __launch_bounds__(256) void gemm_gx_kernel(
    const float* __restrict__ X,     // [32768, 1024]
    const float* __restrict__ W,     // [4096, 1024]
    const float* __restrict__ bih,
    const float* __restrict__ bhh)
{
    __shared__ __align__(16) float As[16][128];
    __shared__ __align__(16) float Bs[16][128];
    const int bm = blockIdx.y * 128;
    const int bn = blockIdx.x * 128;
    const int tid = threadIdx.x;
    const int trow = (tid >> 4) << 3;
    const int tcol = (tid & 15) << 3;

    // accp[p][j]: rows (trow+2p, trow+2p+1), col (tcol+j), packed fp32x2
    uint64_t accp[4][8];
#pragma unroll
    for (int p = 0; p < 4; p++)
#pragma unroll
        for (int j = 0; j < 8; j++) accp[p][j] = 0ull;

    for (int k0 = 0; k0 < DD; k0 += 16) {
#pragma unroll
        for (int i = 0; i < 2; i++) {
            int idx = tid + (i << 8);
            int row = idx >> 2;
            int kv  = (idx & 3) << 2;
            float4 a = *(const float4*)(X + (size_t)(bm + row) * DD + k0 + kv);
            As[kv + 0][row] = a.x; As[kv + 1][row] = a.y;
            As[kv + 2][row] = a.z; As[kv + 3][row] = a.w;
            float4 b = *(const float4*)(W + (size_t)(bn + row) * DD + k0 + kv);
            Bs[kv + 0][row] = b.x; Bs[kv + 1][row] = b.y;
            Bs[kv + 2][row] = b.z; Bs[kv + 3][row] = b.w;
        }
        __syncthreads();
#pragma unroll
        for (int k = 0; k < 16; k++) {
            // a rows as packed pairs (free: contiguous in As)
            ulonglong2 a01 = *(const ulonglong2*)&As[k][trow];
            ulonglong2 a23 = *(const ulonglong2*)&As[k][trow + 4];
            uint64_t ap[4] = {a01.x, a01.y, a23.x, a23.y};
            float4 b0 = *(const float4*)&Bs[k][tcol];
            float4 b1 = *(const float4*)&Bs[k][tcol + 4];
            uint64_t bd[8];
            DUP2(bd[0], b0.x); DUP2(bd[1], b0.y);
            DUP2(bd[2], b0.z); DUP2(bd[3], b0.w);
            DUP2(bd[4], b1.x); DUP2(bd[5], b1.y);
            DUP2(bd[6], b1.z); DUP2(bd[7], b1.w);
#pragma unroll
            for (int p = 0; p < 4; p++)
#pragma unroll
                for (int j = 0; j < 8; j++)
                    FFMA2(accp[p][j], ap[p], bd[j]);
        }
        __syncthreads();
    }

#pragma unroll
    for (int p = 0; p < 4; p++) {
#pragma unroll
        for (int j = 0; j < 8; j++) {
            float lo, hi;
            UNPK2(lo, hi, accp[p][j]);
            int n = bn + tcol + j;
            size_t m0 = (size_t)(bm + trow + 2 * p);
            g_gx[m0 * GG + n]        = lo + bih[n] + bhh[n];
            g_gx[(m0 + 1) * GG + n]  = hi + bih[n] + bhh[n];
        }
    }
}

// ---------------------------------------------------------------------------
// Phase 2: persistent recurrence kernel. 128 CTAs (1/SM), 256 threads.
// CTA owns h-columns j0..j0+7 across all 4 gates (32 gathered w_hh rows) in
// SMEM for the whole kernel. Cell state c in registers. Grid barrier per step.
// Inner product uses FFMA2 with row-pair packed h (free from LDS.128).
// ---------------------------------------------------------------------------
__global__ __launch_bounds__(256, 1) void lstm_persist_kernel(
    const float* __restrict__ W,    // w_hh [4096, 1024]
    const float* __restrict__ h0,
    const float* __restrict__ c0,
    float* __restrict__ out)
{
    extern __shared__ float smem[];
    float* Ws = smem;                 // [1024][32], col swizzled by (k&28)
    float* Hsb = smem + 1024 * 32;    // [2][64][64], col swizzled by (k&28)

    const int tid = threadIdx.x;
    const int tx  = tid & 15;         // out col pair 2tx,2tx+1
    const int ty  = tid >> 4;         // out rows 4ty..4ty+3
    const int j0  = blockIdx.x * 8;

    const unsigned rel_base = *(volatile unsigned*)&g_release;

    // ---- Load W slice into SMEM (once) ----
#pragma unroll 4
    for (int r = 0; r < 32; r++) {
        int idx = r * 256 + tid;
        int k4  = idx & 255;
        int c   = idx >> 8;
        int k   = k4 << 2;
        int row = (c >> 3) * HH + j0 + (c & 7);
        float4 v = *(const float4*)(W + (size_t)row * HH + k);
        int col = c ^ (k & 28);
        Ws[(k + 0) * 32 + col] = v.x;
        Ws[(k + 1) * 32 + col] = v.y;
        Ws[(k + 2) * 32 + col] = v.z;
        Ws[(k + 3) * 32 + col] = v.w;
    }

    // ---- Cell state in registers ----
    float c_reg[2];
#pragma unroll
    for (int i = 0; i < 2; i++) {
        int idx = tid + (i << 8);
        int b = idx >> 3, jl = idx & 7;
        c_reg[i] = c0[(size_t)b * HH + j0 + jl];
    }
    __syncthreads();

    const int hkv = tx << 2;          // local k offset 0..60

    for (int t = 0; t < TT; t++) {
        const float* __restrict__ h_in =
            (t == 0) ? h0 : out + (size_t)(t - 1) * BB * HH;
        const float* __restrict__ gx = g_gx + (size_t)t * BB * GG;

        // Prefetch gx (hidden under FMA work)
        float gpre[2][4];
#pragma unroll
        for (int i = 0; i < 2; i++) {
            int idx = tid + (i << 8);
            int b = idx >> 3, jl = idx & 7;
            const float* gr = gx + (size_t)b * GG + j0 + jl;
#pragma unroll
            for (int g = 0; g < 4; g++) gpre[i][g] = gr[g * HH];
        }

        // accp[p][j]: rows (4ty+2p, 4ty+2p+1), col (2tx+j), packed fp32x2
        uint64_t acc00 = 0ull, acc01 = 0ull, acc10 = 0ull, acc11 = 0ull;

        // Preload tile 0
        {
            const float* hsrc = h_in + hkv;
#pragma unroll
            for (int r = 0; r < 4; r++) {
                float4 v = *(const float4*)(hsrc + (size_t)(ty + 16 * r) * HH);
                int col = (ty + 16 * r) ^ (hkv & 28);
                float* dst = Hsb + (hkv * 64) + col;
                dst[0]   = v.x; dst[64]  = v.y;
                dst[128] = v.z; dst[192] = v.w;
            }
        }
        __syncthreads();

        for (int it = 0; it < 16; ++it) {
            float4 pre[4];
            if (it < 15) {
                const float* hsrc = h_in + (it + 1) * 64 + hkv;
#pragma unroll
                for (int r = 0; r < 4; r++)
                    pre[r] = *(const float4*)(hsrc + (size_t)(ty + 16 * r) * HH);
            }
            const float* cur = Hsb + (it & 1) * 4096;
            const float* WsK = Ws + (it * 64) * 32;
#pragma unroll
            for (int kk = 0; kk < 64; kk++) {
                int kq = kk & 28;
                float2 w2 = *(const float2*)(WsK + kk * 32 + ((2 * tx) ^ kq));
                ulonglong2 hp = *(const ulonglong2*)(cur + kk * 64 + ((4 * ty) ^ kq));
                uint64_t wxx, wyy;
                DUP2(wxx, w2.x);
                DUP2(wyy, w2.y);
                FFMA2(acc00, hp.x, wxx);
                FFMA2(acc01, hp.x, wyy);
                FFMA2(acc10, hp.y, wxx);
                FFMA2(acc11, hp.y, wyy);
            }
            __syncthreads();
            if (it < 15) {
                float* nxt = Hsb + ((it + 1) & 1) * 4096;
#pragma unroll
                for (int r = 0; r < 4; r++) {
                    int col = (ty + 16 * r) ^ (hkv & 28);
                    float* dst = nxt + hkv * 64 + col;
                    dst[0]   = pre[r].x; dst[64]  = pre[r].y;
                    dst[128] = pre[r].z; dst[192] = pre[r].w;
                }
                __syncthreads();
            }
        }

        // Unpack accumulators: acc[r][j] with rows 4ty+r
        float accf[4][2];
        UNPK2(accf[0][0], accf[1][0], acc00);
        UNPK2(accf[0][1], accf[1][1], acc01);
        UNPK2(accf[2][0], accf[3][0], acc10);
        UNPK2(accf[2][1], accf[3][1], acc11);

        // Stage matmul results to smem (stride 33)
        float* sg = Hsb;
#pragma unroll
        for (int r = 0; r < 4; r++) {
#pragma unroll
            for (int jj = 0; jj < 2; jj++)
                sg[(4 * ty + r) * 33 + (2 * tx + jj)] = accf[r][jj];
        }
        __syncthreads();

        // Pointwise LSTM cell
        float* h_out = out + (size_t)t * BB * HH;
#pragma unroll
        for (int i = 0; i < 2; i++) {
            int idx = tid + (i << 8);
            int b = idx >> 3, jl = idx & 7;
            float gi = sg[b * 33 + jl]      + gpre[i][0];
            float gf = sg[b * 33 + 8 + jl]  + gpre[i][1];
            float gg = sg[b * 33 + 16 + jl] + gpre[i][2];
            float go = sg[b * 33 + 24 + jl] + gpre[i][3];
            float ig = 1.0f / (1.0f + __expf(-gi));
            float fg = 1.0f / (1.0f + __expf(-gf));
            float gv = tanhf(gg);
            float og = 1.0f / (1.0f + __expf(-go));
            float cn = fg * c_reg[i] + ig * gv;
            float hn = og * tanhf(cn);
            c_reg[i] = cn;
            h_out[(size_t)b * HH + j0 + jl] = hn;
            if (t == TT - 1) {
                out[(size_t)TT * BB * HH + (size_t)b * HH + j0 + jl] = hn;
                out[(size_t)TT * BB * HH + BB * HH + (size_t)b * HH + j0 + jl] = cn;
            }
        }

        // Grid-wide barrier
        if (t < TT - 1) {
            __threadfence();
            __syncthreads();
            if (tid == 0) {
                unsigned target = rel_base + (unsigned)(t + 1);
                unsigned old = atomicAdd(&g_arrive, 1);
                if (old == NCTA - 1) {
                    g_arrive = 0;
                    __threadfence();
                    *(volatile unsigned*)&g_release = target;
                } else {
                    while ((int)(*(volatile unsigned*)&g_release - target) < 0) {}
                    __threadfence();
                }
            }
            __syncthreads();
        }
    }
}

extern "C" void kernel_launch(void* const* d_in, const int* in_sizes, int n_in,
                              void* d_out, int out_size)
{
    const float* x    = (const float*)d_in[0];
    const float* h0   = (const float*)d_in[1];
    const float* c0   = (const float*)d_in[2];
    const float* w_ih = (const float*)d_in[3];
    const float* b_ih = (const float*)d_in[4];
    const float* w_hh = (const float*)d_in[5];
    const float* b_hh = (const float*)d_in[6];
    float* out = (float*)d_out;

    (void)in_sizes; (void)n_in; (void)out_size;

    // Phase 1: big input-projection GEMM (biases folded)
    dim3 g1(GG / 128, (TT * BB) / 128);
    gemm_gx_kernel<<<g1, 256>>>(x, w_ih, b_ih, b_hh);

    // Phase 2: persistent recurrence (whole scan in one kernel)
    const int smem_bytes = (1024 * 32 + 2 * 64 * 64) * (int)sizeof(float); // 160 KB
    cudaFuncSetAttribute(lstm_persist_kernel,
                         cudaFuncAttributeMaxDynamicSharedMemorySize, smem_bytes);
    lstm_persist_kernel<<<NCTA, 256, smem_bytes>>>(w_hh, h0, c0, out);
}